// round 8
// baseline (speedup 1.0000x reference)
#include <cuda_runtime.h>
#include <cuda_bf16.h>

// Shapes (dataset-fixed):
//   embeddings: (4096, 1024) f32
//   labels:     (4096,)      i64 OR i32  (JAX x64-downgrade — detected at runtime)
//   queue:      (100, 256, 1024) f32
//   queue_ptr:  (100,)       i64 OR i32  (same dtype family as labels)
//   out:        (100, 256, 1024) f32
//
// Semantics: k-th occurrence of class c (batch order) is written, L2-normalized,
// at queue slot (queue_ptr[c] + k) % 256. All other rows pass through unchanged.

#define FEAT 1024
#define MAX_ROWS (100 * 256)

// Inverse scatter map: g_mask[c*Q + slot] = batch index writing that row, or -1.
__device__ int g_mask[MAX_ROWS];

// ---------------------------------------------------------------------------
// Detect whether an integer buffer is int64 or int32.
// Values are small (< 2^31). Read first 8 words as i64:
//   true int64  -> every word < 2^32
//   int32 pairs -> some word has a nonzero high half (P(miss) ~ 1e-16 for labels)
// ---------------------------------------------------------------------------
__device__ __forceinline__ bool detect_is64(const void* p) {
    const unsigned long long* q = (const unsigned long long*)p;
    bool is64 = true;
    #pragma unroll
    for (int i = 0; i < 8; i++)
        if (q[i] > 0xFFFFFFFFull) is64 = false;
    return is64;
}

__device__ __forceinline__ int load_idx(const void* p, int i, bool is64) {
    return is64 ? (int)((const long long*)p)[i] : ((const int*)p)[i];
}

// ---------------------------------------------------------------------------
// Kernel 1: fused clear + per-class serial-FIFO rank.
// One warp per class; warp c is the ONLY writer of g_mask[c*Q .. c*Q+Q).
// Scanning labels in batch order makes duplicate-slot writes (queue wrap)
// land in increasing batch order = last-write-wins, matching .at[].set.
// ---------------------------------------------------------------------------
__global__ void rank_kernel(const void* __restrict__ labels,
                            const void* __restrict__ qptr,
                            int B, int C, int Q) {
    int warp = (blockIdx.x * blockDim.x + threadIdx.x) >> 5;
    int lane = threadIdx.x & 31;
    if (warp >= C) return;
    int c = warp;

    const bool is64 = detect_is64(labels);   // labels & qptr share dtype family

    // Clear this class's slice of the inverse map (graph replays -> every call).
    for (int s = lane; s < Q; s += 32)
        g_mask[c * Q + s] = -1;
    __syncwarp();

    int base = load_idx(qptr, c, is64) % Q;
    if (base < 0) base += Q;

    int count = 0;
    for (int i0 = 0; i0 < B; i0 += 32) {
        int i = i0 + lane;
        bool m = false;
        if (i < B) m = (load_idx(labels, i, is64) == c);
        unsigned bal = __ballot_sync(0xffffffffu, m);
        if (m) {
            int rank = count + __popc(bal & ((1u << lane) - 1u));
            int slot = (base + rank) % Q;
            g_mask[c * Q + slot] = i;
        }
        count += __popc(bal);
    }
}

// ---------------------------------------------------------------------------
// Kernel 2: fused copy + normalize-scatter. One CTA of 128 threads per 4 KB
// output row; each thread handles TWO float4s (MLP_p1 = 2).
//   src < 0  -> stream-copy queue row (.cs, single-touch)
//   src >= 0 -> read embeddings[src], block-reduce ||x||^2, write x/max(||x||,eps)
// Branch is uniform per CTA (src is per-row), so __syncthreads is safe.
// ---------------------------------------------------------------------------
__global__ __launch_bounds__(128) void write_rows_kernel(
        const float4* __restrict__ emb,
        const float4* __restrict__ queue,
        float4* __restrict__ out) {
    const int row = blockIdx.x;
    const int t   = threadIdx.x;               // 0..127
    const int src = __ldg(&g_mask[row]);

    const size_t vrow = (size_t)row * (FEAT / 4);
    const int i0 = t;
    const int i1 = t + 128;
    float4 a, b;

    if (src >= 0) {
        const size_t erow = (size_t)src * (FEAT / 4);
        a = __ldg(&emb[erow + i0]);
        b = __ldg(&emb[erow + i1]);
        float ss = a.x * a.x + a.y * a.y + a.z * a.z + a.w * a.w
                 + b.x * b.x + b.y * b.y + b.z * b.z + b.w * b.w;

        #pragma unroll
        for (int off = 16; off > 0; off >>= 1)
            ss += __shfl_xor_sync(0xffffffffu, ss, off);

        __shared__ float red[4];
        int wid = t >> 5, lane = t & 31;
        if (lane == 0) red[wid] = ss;
        __syncthreads();
        float total = red[0] + red[1] + red[2] + red[3];

        float scale = 1.0f / fmaxf(sqrtf(total), 1e-12f);
        a.x *= scale; a.y *= scale; a.z *= scale; a.w *= scale;
        b.x *= scale; b.y *= scale; b.z *= scale; b.w *= scale;
    } else {
        a = __ldcs(&queue[vrow + i0]);
        b = __ldcs(&queue[vrow + i1]);
    }
    __stcs(&out[vrow + i0], a);
    __stcs(&out[vrow + i1], b);
}

// ---------------------------------------------------------------------------
extern "C" void kernel_launch(void* const* d_in, const int* in_sizes, int n_in,
                              void* d_out, int out_size) {
    // Identify inputs by element count (robust to metadata ordering):
    //   queue == out_size (26.2M), embeddings ~4.19M, labels 4096, queue_ptr 100.
    const void *embp = 0, *queuep = 0, *labelsp = 0, *qptrp = 0;
    int emb_count = 0;
    for (int i = 0; i < n_in; i++) {
        int s = in_sizes[i];
        if (s == out_size)      queuep  = d_in[i];
        else if (s > 100000)  { embp    = d_in[i]; emb_count = s; }
        else if (s > 1000)      labelsp = d_in[i];
        else                    qptrp   = d_in[i];
    }

    float* out = (float*)d_out;
    const int B      = emb_count / FEAT;       // 4096
    const int n_rows = out_size / FEAT;        // 25600
    const int C      = 100;                    // classes (qptr count)
    // find qptr count for C (robustness): smallest input
    for (int i = 0; i < n_in; i++)
        if (d_in[i] == qptrp) { /* C = in_sizes[i]; */ }
    const int Q = n_rows / C;                  // 256

    int rank_blocks = (C + 7) / 8;             // one warp/class, 8 warps/block
    rank_kernel<<<rank_blocks, 256>>>(labelsp, qptrp, B, C, Q);

    write_rows_kernel<<<n_rows, 128>>>((const float4*)embp,
                                       (const float4*)queuep,
                                       (float4*)out);
}

// round 10
// speedup vs baseline: 1.3459x; 1.3459x over previous
#include <cuda_runtime.h>
#include <cuda_bf16.h>

// Shapes (dataset-fixed):
//   embeddings: (4096, 1024) f32
//   labels:     (4096,)      i64 OR i32 (JAX x64-downgrade — detected at runtime)
//   queue:      (100, 256, 1024) f32
//   queue_ptr:  (100,)       i64 OR i32
//   out:        (100, 256, 1024) f32

#define FEAT 1024
#define MAX_ROWS (100 * 256)
#define MAX_B 4096

// Inverse scatter map: g_mask[c*Q + slot] = batch index writing that row, or -1.
__device__ int g_mask[MAX_ROWS];

__device__ __forceinline__ bool detect_is64(const void* p) {
    const unsigned long long* q = (const unsigned long long*)p;
    bool is64 = true;
    #pragma unroll
    for (int i = 0; i < 8; i++)
        if (q[i] > 0xFFFFFFFFull) is64 = false;
    return is64;
}

__device__ __forceinline__ int load_idx(const void* p, int i, bool is64) {
    return is64 ? (int)((const long long*)p)[i] : ((const int*)p)[i];
}

// ---------------------------------------------------------------------------
// Kernel 1: fused clear + per-class serial-FIFO rank, with labels staged in
// shared memory. Each block: 256 threads cooperatively load all B labels into
// smem (one coalesced pass), then its 8 warps each scan one class from smem
// (LDS 29cyc vs L2 ~250cyc -> serial chain is ballot-limited, ~35 cyc/iter).
// Warp c is the ONLY writer of g_mask[c*Q..c*Q+Q): clear + scatter race-free.
// Batch-order scan => duplicate-slot (wraparound) writes are last-write-wins,
// matching .at[].set.
// ---------------------------------------------------------------------------
__global__ __launch_bounds__(256) void rank_kernel(
        const void* __restrict__ labels,
        const void* __restrict__ qptr,
        int B, int C, int Q) {
    __shared__ int s_lab[MAX_B];

    const bool is64 = detect_is64(labels);   // labels & qptr share dtype family
    const int tid = threadIdx.x;

    // Stage labels (coalesced, 16 independent loads/thread).
    for (int j = tid; j < B; j += 256)
        s_lab[j] = load_idx(labels, j, is64);
    __syncthreads();

    const int warp = blockIdx.x * 8 + (tid >> 5);
    const int lane = tid & 31;
    if (warp >= C) return;
    const int c = warp;

    // Clear this class's slice of the inverse map (graph replays -> every call).
    for (int s = lane; s < Q; s += 32)
        g_mask[c * Q + s] = -1;
    __syncwarp();

    int base = load_idx(qptr, c, is64) % Q;
    if (base < 0) base += Q;

    const unsigned lanemask_lt = (1u << lane) - 1u;
    int count = 0;
    #pragma unroll 8
    for (int i0 = 0; i0 < B; i0 += 32) {
        int i = i0 + lane;
        bool m = (i < B) && (s_lab[i] == c);
        unsigned bal = __ballot_sync(0xffffffffu, m);
        if (m) {
            int rank = count + __popc(bal & lanemask_lt);
            int slot = (base + rank) % Q;
            g_mask[c * Q + slot] = i;
        }
        count += __popc(bal);
    }
}

// ---------------------------------------------------------------------------
// Kernel 2: fused copy + normalize-scatter. One CTA of 128 threads per 4 KB
// output row; each thread handles TWO float4s.
// The queue-row loads are issued UNCONDITIONALLY, in parallel with the mask
// load, so the CTA front is one memory round-trip instead of a serialized
// mask->branch->load chain (issue% was 10.8, DRAM% 65.6 -> latency-bound).
// Normalize rows (~16%) discard the queue data: +8% traffic for -1 dependency.
// ---------------------------------------------------------------------------
__global__ __launch_bounds__(128) void write_rows_kernel(
        const float4* __restrict__ emb,
        const float4* __restrict__ queue,
        float4* __restrict__ out) {
    const int row = blockIdx.x;
    const int t   = threadIdx.x;               // 0..127
    const size_t vrow = (size_t)row * (FEAT / 4);
    const int i0 = t;
    const int i1 = t + 128;

    // All three loads issue back-to-back (no dependencies).
    float4 a = __ldcs(&queue[vrow + i0]);
    float4 b = __ldcs(&queue[vrow + i1]);
    const int src = __ldg(&g_mask[row]);

    if (src >= 0) {
        const size_t erow = (size_t)src * (FEAT / 4);
        a = __ldg(&emb[erow + i0]);
        b = __ldg(&emb[erow + i1]);
        float ss = a.x * a.x + a.y * a.y + a.z * a.z + a.w * a.w
                 + b.x * b.x + b.y * b.y + b.z * b.z + b.w * b.w;

        #pragma unroll
        for (int off = 16; off > 0; off >>= 1)
            ss += __shfl_xor_sync(0xffffffffu, ss, off);

        __shared__ float red[4];
        int wid = t >> 5, lane = t & 31;
        if (lane == 0) red[wid] = ss;
        __syncthreads();
        float total = red[0] + red[1] + red[2] + red[3];

        float scale = 1.0f / fmaxf(sqrtf(total), 1e-12f);
        a.x *= scale; a.y *= scale; a.z *= scale; a.w *= scale;
        b.x *= scale; b.y *= scale; b.z *= scale; b.w *= scale;
    }
    __stcs(&out[vrow + i0], a);
    __stcs(&out[vrow + i1], b);
}

// ---------------------------------------------------------------------------
extern "C" void kernel_launch(void* const* d_in, const int* in_sizes, int n_in,
                              void* d_out, int out_size) {
    // Identify inputs by element count (robust to ordering):
    //   queue == out_size (26.2M), embeddings ~4.19M, labels 4096, queue_ptr 100.
    const void *embp = 0, *queuep = 0, *labelsp = 0, *qptrp = 0;
    int emb_count = 0, C = 100;
    for (int i = 0; i < n_in; i++) {
        int s = in_sizes[i];
        if (s == out_size)      queuep  = d_in[i];
        else if (s > 100000)  { embp    = d_in[i]; emb_count = s; }
        else if (s > 1000)      labelsp = d_in[i];
        else                  { qptrp   = d_in[i]; C = s; }
    }

    float* out = (float*)d_out;
    const int B      = emb_count / FEAT;       // 4096
    const int n_rows = out_size / FEAT;        // 25600
    const int Q      = n_rows / C;             // 256

    int rank_blocks = (C + 7) / 8;             // one warp/class, 8 warps/block
    rank_kernel<<<rank_blocks, 256>>>(labelsp, qptrp, B, C, Q);

    write_rows_kernel<<<n_rows, 128>>>((const float4*)embp,
                                       (const float4*)queuep,
                                       (float4*)out);
}